// round 5
// baseline (speedup 1.0000x reference)
#include <cuda_runtime.h>
#include <math.h>

#define NN_ 1536
#define DD_ 768
#define HH_ 64
#define PLANE (NN_ * NN_)
#define KSPLIT 12

// Scratch (fully overwritten every launch -> graph-replay safe)
__device__ float g_part[KSPLIT * NN_ * 128]; // k-split partials of E@[W1a|W1b]
__device__ float g_A[NN_ * HH_];             // ha - g
__device__ float g_B[NN_ * HH_];             // hb + g + b1
__device__ float g_pv[NN_ * 6];              // pos(3), vel(3)

// ---------------------------------------------------------------------------
// Kernel 1: partial GEMM. grid (48, KSPLIT), 256 threads.
// Block (rb, ks): rows rb*32..+31, k-chunk ks*64..+63, 128 output cols
// (cols 0..63 = W1a contribution, 64..127 = W1b contribution).
// Per thread: 4 rows x 4 cols. E tile stored k-major (transposed): per kk the
// 4 e-values are one broadcast LDS.128.
// ---------------------------------------------------------------------------
__global__ __launch_bounds__(256) void gemm_partial_kernel(
    const float* __restrict__ E, const float* __restrict__ W1)
{
    __shared__ __align__(16) float sET[16 * 36];  // [kk][row], 32 rows + pad 4
    __shared__ __align__(16) float sW[16 * 128];  // [kk][h2]

    const int t    = threadIdx.x;
    const int rb   = blockIdx.x;
    const int ks   = blockIdx.y;
    const int lane = t & 31;   // col group: cols lane*4..+3
    const int wrp  = t >> 5;   // row group: rows wrp*4..+3 (8 warps x 4 rows)

    float4 acc[4];
#pragma unroll
    for (int r = 0; r < 4; ++r) acc[r] = make_float4(0.f, 0.f, 0.f, 0.f);

    const float4* E4  = reinterpret_cast<const float4*>(E);
    const float4* W4g = reinterpret_cast<const float4*>(W1);

    for (int kt = 0; kt < 4; ++kt) {
        const int kbase = ks * 64 + kt * 16;

        // fill sET (transposed): threads 0..127, one float4 of E each
        if (t < 128) {
            int row = t >> 2, c4 = t & 3;
            float4 v = E4[((rb * 32 + row) * DD_ + kbase) / 4 + c4];
            sET[(c4 * 4 + 0) * 36 + row] = v.x;
            sET[(c4 * 4 + 1) * 36 + row] = v.y;
            sET[(c4 * 4 + 2) * 36 + row] = v.z;
            sET[(c4 * 4 + 3) * 36 + row] = v.w;
        }
        // fill sW: 512 float4, 2 per thread
#pragma unroll
        for (int idx = t; idx < 512; idx += 256) {
            int kk = idx >> 5, c4 = idx & 31;
            float4 v = (c4 < 16) ? W4g[((kbase + kk) * 64) / 4 + c4]
                                 : W4g[((DD_ + kbase + kk) * 64) / 4 + (c4 - 16)];
            reinterpret_cast<float4*>(sW)[kk * 32 + c4] = v;
        }
        __syncthreads();

        const float4* sET4 = reinterpret_cast<const float4*>(sET);
        const float4* sW4  = reinterpret_cast<const float4*>(sW);
#pragma unroll
        for (int kk = 0; kk < 16; ++kk) {
            float4 w = sW4[kk * 32 + lane];
            float4 e = sET4[kk * 9 + wrp];            // rows wrp*4..+3
            acc[0].x = fmaf(e.x, w.x, acc[0].x);
            acc[0].y = fmaf(e.x, w.y, acc[0].y);
            acc[0].z = fmaf(e.x, w.z, acc[0].z);
            acc[0].w = fmaf(e.x, w.w, acc[0].w);
            acc[1].x = fmaf(e.y, w.x, acc[1].x);
            acc[1].y = fmaf(e.y, w.y, acc[1].y);
            acc[1].z = fmaf(e.y, w.z, acc[1].z);
            acc[1].w = fmaf(e.y, w.w, acc[1].w);
            acc[2].x = fmaf(e.z, w.x, acc[2].x);
            acc[2].y = fmaf(e.z, w.y, acc[2].y);
            acc[2].z = fmaf(e.z, w.z, acc[2].z);
            acc[2].w = fmaf(e.z, w.w, acc[2].w);
            acc[3].x = fmaf(e.w, w.x, acc[3].x);
            acc[3].y = fmaf(e.w, w.y, acc[3].y);
            acc[3].z = fmaf(e.w, w.z, acc[3].z);
            acc[3].w = fmaf(e.w, w.w, acc[3].w);
        }
        __syncthreads();
    }

    float4* dst = reinterpret_cast<float4*>(g_part) + (size_t)ks * (NN_ * 32);
    const int rbase = rb * 32 + wrp * 4;
#pragma unroll
    for (int r = 0; r < 4; ++r)
        dst[(rbase + r) * 32 + lane] = acc[r];
}

// ---------------------------------------------------------------------------
// Kernel 2: reduce partials + fold geometry terms. grid 384, block (64,4).
// ---------------------------------------------------------------------------
__global__ __launch_bounds__(256) void fold_kernel(
    const float* __restrict__ pos, const float* __restrict__ prev,
    const float* __restrict__ W1, const float* __restrict__ b1)
{
    const int i = blockIdx.x * 4 + threadIdx.y;
    const int h = threadIdx.x;

    float suma = 0.f, sumb = 0.f;
#pragma unroll
    for (int s = 0; s < KSPLIT; ++s) {
        suma += g_part[(size_t)s * (NN_ * 128) + i * 128 + h];
        sumb += g_part[(size_t)s * (NN_ * 128) + i * 128 + 64 + h];
    }
    float px = pos[i * 3 + 0], py = pos[i * 3 + 1], pz = pos[i * 3 + 2];
    float vx = px - prev[i * 3 + 0];
    float vy = py - prev[i * 3 + 1];
    float vz = pz - prev[i * 3 + 2];

    const float* Ws = W1 + 2 * DD_ * 64;  // W1s rows (8 x 64)
    float g = px * Ws[0 * 64 + h] + py * Ws[1 * 64 + h] + pz * Ws[2 * 64 + h]
            + vx * Ws[4 * 64 + h] + vy * Ws[5 * 64 + h] + vz * Ws[6 * 64 + h]
            + py * Ws[7 * 64 + h];

    g_A[i * 64 + h] = suma - g;
    g_B[i * 64 + h] = sumb + g + b1[h];

    if (h == 0) {
        g_pv[i * 6 + 0] = px; g_pv[i * 6 + 1] = py; g_pv[i * 6 + 2] = pz;
        g_pv[i * 6 + 3] = vx; g_pv[i * 6 + 4] = vy; g_pv[i * 6 + 5] = vz;
    }
}

// ---------------------------------------------------------------------------
// Kernel 3: pairwise. grid (48, 48), block (16, 16). Each thread: 2x2 strided
// micro-tile i in {ty, ty+16}, j in {tx, tx+16}.
// Logits as softmax-invariant differences: delta_k = l_k - l_0 using
// W2d[h][k] = W2[h][k+1] - W2[h][0]  (3 accumulators per pair, not 4).
// ---------------------------------------------------------------------------
__global__ __launch_bounds__(256) void pair_kernel(
    const float* __restrict__ W1, const float* __restrict__ W2,
    const float* __restrict__ b2, float* __restrict__ out)
{
    __shared__ __align__(16) float sA[32 * 68];   // rows padded to 68 floats
    __shared__ __align__(16) float sB[32 * 68];
    __shared__ __align__(16) float4 sW2d[64];     // (d1,d2,d3,0) per h
    __shared__ __align__(16) float sW3[64];
    __shared__ float sPVi[32 * 6];
    __shared__ float sPVj[32 * 6];

    const int tx = threadIdx.x, ty = threadIdx.y;
    const int t  = ty * 16 + tx;
    const int i0 = blockIdx.y * 32;
    const int j0 = blockIdx.x * 32;

    for (int idx = t; idx < 512; idx += 256) {
        int r = idx >> 4, c = idx & 15;
        reinterpret_cast<float4*>(sA)[r * 17 + c] =
            reinterpret_cast<const float4*>(g_A)[(i0 + r) * 16 + c];
        reinterpret_cast<float4*>(sB)[r * 17 + c] =
            reinterpret_cast<const float4*>(g_B)[(j0 + r) * 16 + c];
    }
    if (t < 64) {
        float w0 = W2[t * 4 + 0];
        sW2d[t] = make_float4(W2[t * 4 + 1] - w0, W2[t * 4 + 2] - w0,
                              W2[t * 4 + 3] - w0, 0.f);
        sW3[t] = W1[(2 * DD_ + 3) * 64 + t];  // w3 = W1s row 3 (distance)
    }
    for (int idx = t; idx < 192; idx += 256) {
        sPVi[idx] = g_pv[i0 * 6 + idx];
        sPVj[idx] = g_pv[j0 * 6 + idx];
    }
    __syncthreads();

    // geometry for the 4 pairs
    float dist[4], clos[4], vdif[4];
#pragma unroll
    for (int p = 0; p < 2; ++p) {
        int ri = ty + p * 16;
        float pix = sPVi[ri * 6 + 0], piy = sPVi[ri * 6 + 1], piz = sPVi[ri * 6 + 2];
        float vix = sPVi[ri * 6 + 3], viy = sPVi[ri * 6 + 4], viz = sPVi[ri * 6 + 5];
#pragma unroll
        for (int q = 0; q < 2; ++q) {
            int rj = tx + q * 16;
            float rpx = sPVj[rj * 6 + 0] - pix;
            float rpy = sPVj[rj * 6 + 1] - piy;
            float rpz = sPVj[rj * 6 + 2] - piz;
            float rvx = sPVj[rj * 6 + 3] - vix;
            float rvy = sPVj[rj * 6 + 4] - viy;
            float rvz = sPVj[rj * 6 + 5] - viz;
            float d = sqrtf(rpx * rpx + rpy * rpy + rpz * rpz);
            float dot = rpx * rvx + rpy * rvy + rpz * rvz;
            int pq = p * 2 + q;
            dist[pq] = d;
            clos[pq] = -dot / fmaxf(d, 1e-6f);
            vdif[pq] = rpy;
        }
    }

    float acc1[4] = {0.f, 0.f, 0.f, 0.f};
    float acc2[4] = {0.f, 0.f, 0.f, 0.f};
    float acc3[4] = {0.f, 0.f, 0.f, 0.f};

    const float4* A4  = reinterpret_cast<const float4*>(sA);
    const float4* B4  = reinterpret_cast<const float4*>(sB);
    const float4* W34 = reinterpret_cast<const float4*>(sW3);

#pragma unroll 4
    for (int h4 = 0; h4 < 16; ++h4) {
        float4 af[2], bf[2];
        af[0] = A4[ty * 17 + h4];
        af[1] = A4[(ty + 16) * 17 + h4];
        bf[0] = B4[tx * 17 + h4];
        bf[1] = B4[(tx + 16) * 17 + h4];
        float4 w3v = W34[h4];
        float4 wd0 = sW2d[h4 * 4 + 0];
        float4 wd1 = sW2d[h4 * 4 + 1];
        float4 wd2 = sW2d[h4 * 4 + 2];
        float4 wd3 = sW2d[h4 * 4 + 3];

        const float aw[2][4] = {{af[0].x, af[0].y, af[0].z, af[0].w},
                                {af[1].x, af[1].y, af[1].z, af[1].w}};
        const float bw[2][4] = {{bf[0].x, bf[0].y, bf[0].z, bf[0].w},
                                {bf[1].x, bf[1].y, bf[1].z, bf[1].w}};
        const float w3a[4] = {w3v.x, w3v.y, w3v.z, w3v.w};
        const float4 wda[4] = {wd0, wd1, wd2, wd3};

#pragma unroll
        for (int hh = 0; hh < 4; ++hh) {
            const float w3h = w3a[hh];
            const float4 wd = wda[hh];
#pragma unroll
            for (int p = 0; p < 2; ++p) {
#pragma unroll
                for (int q = 0; q < 2; ++q) {
                    const int pq = p * 2 + q;
                    float tt = fmaf(dist[pq], w3h, aw[p][hh] + bw[q][hh]);
                    float r  = fmaxf(tt, 0.f);
                    acc1[pq] = fmaf(r, wd.x, acc1[pq]);
                    acc2[pq] = fmaf(r, wd.y, acc2[pq]);
                    acc3[pq] = fmaf(r, wd.z, acc3[pq]);
                }
            }
        }
    }

    const float db1 = __ldg(&b2[1]) - __ldg(&b2[0]);
    const float db2 = __ldg(&b2[2]) - __ldg(&b2[0]);
    const float db3 = __ldg(&b2[3]) - __ldg(&b2[0]);

#pragma unroll
    for (int p = 0; p < 2; ++p) {
#pragma unroll
        for (int q = 0; q < 2; ++q) {
            const int pq = p * 2 + q;
            float d1 = acc1[pq] + db1;
            float d2 = acc2[pq] + db2;
            float d3 = acc3[pq] + db3;
            float m = fmaxf(fmaxf(0.f, d1), fmaxf(d2, d3));
            float sum = __expf(0.f - m) + __expf(d1 - m)
                      + __expf(d2 - m) + __expf(d3 - m);
            float conf = __fdividef(1.0f, sum);
            int best = 0; float bm = 0.f;
            if (d1 > bm) { bm = d1; best = 1; }
            if (d2 > bm) { bm = d2; best = 2; }
            if (d3 > bm) { bm = d3; best = 3; }

            float d = dist[pq], c = clos[pq], v = vdif[pq];
            bool near  = d < 0.25f;
            bool appr  = !near && (c > 0.05f);
            bool flee  = !near && !appr && (c < -0.05f);
            bool above = !near && !appr && !flee && (fabsf(v) > 0.3f) && (d < 0.5f);

            int rt = near ? 0 : (appr ? 1 : (flee ? 2 : (above ? 3 : best)));
            float co = conf;
            if (near)              co = fmaxf(co, 0.8f);
            else if (appr || flee) co = fmaxf(co, 0.6f);
            else if (above)        co = fmaxf(co, 0.5f);

            int ig = i0 + ty + p * 16;
            int jg = j0 + tx + q * 16;
            size_t off = (size_t)ig * NN_ + jg;
            out[off]             = (float)rt;
            out[PLANE + off]     = co;
            out[2 * PLANE + off] = (jg > ig && co > 0.3f) ? 1.0f : 0.0f;
        }
    }
}

extern "C" void kernel_launch(void* const* d_in, const int* in_sizes, int n_in,
                              void* d_out, int out_size)
{
    const float* E    = (const float*)d_in[0];
    const float* pos  = (const float*)d_in[1];
    const float* prev = (const float*)d_in[2];
    const float* W1   = (const float*)d_in[3];
    const float* b1   = (const float*)d_in[4];
    const float* W2   = (const float*)d_in[5];
    const float* b2   = (const float*)d_in[6];
    float* out = (float*)d_out;

    gemm_partial_kernel<<<dim3(48, KSPLIT), 256>>>(E, W1);
    fold_kernel<<<NN_ / 4, dim3(64, 4)>>>(pos, prev, W1, b1);
    pair_kernel<<<dim3(48, 48), dim3(16, 16)>>>(W1, W2, b2, out);
}

// round 6
// speedup vs baseline: 1.0372x; 1.0372x over previous
#include <cuda_runtime.h>
#include <math.h>

#define NN_ 1536
#define DD_ 768
#define HH_ 64
#define PLANE (NN_ * NN_)
#define KSPLIT 12

// Scratch (fully overwritten every launch -> graph-replay safe)
__device__ float g_part[KSPLIT * NN_ * 128]; // k-split partials of E@[W1a|W1b]
__device__ float g_A[NN_ * HH_];             // ha - g
__device__ float g_B[NN_ * HH_];             // hb + g + b1
__device__ float g_pv[NN_ * 6];              // pos(3), vel(3)

// ---------------------------------------------------------------------------
// Kernel 1: partial GEMM, software-pipelined fills. grid (24, KSPLIT), 256 thr.
// Block (rb, ks): rows rb*64..+63, k-chunk ks*64..+63, 128 output cols
// (cols 0..63 = W1a contribution, 64..127 = W1b contribution).
// Per thread: 8 rows x 4 cols. E tile stored k-major (transposed) so the 8
// e-values per kk are two broadcast LDS.128. LDG for tile kt+1 is issued
// before the compute of tile kt (register prefetch) to hide fill latency.
// ---------------------------------------------------------------------------
__global__ __launch_bounds__(256) void gemm_partial_kernel(
    const float* __restrict__ E, const float* __restrict__ W1)
{
    __shared__ __align__(16) float sET[16 * 68];  // [kk][row], 64 rows + pad 4
    __shared__ __align__(16) float sW[16 * 128];  // [kk][h2]

    const int t    = threadIdx.x;
    const int rb   = blockIdx.x;
    const int ks   = blockIdx.y;
    const int lane = t & 31;   // col group: cols lane*4..+3
    const int wrp  = t >> 5;   // row group: rows wrp*8..+7

    // fill index precompute
    const int erow = t >> 2, ec4 = t & 3;          // E: one float4 per thread
    const int wkk0 = t >> 5, wc0 = t & 31;         // W: two float4 per thread

    const float4* E4  = reinterpret_cast<const float4*>(E);
    const float4* W4g = reinterpret_cast<const float4*>(W1);

    float4 acc[8];
#pragma unroll
    for (int r = 0; r < 8; ++r) acc[r] = make_float4(0.f, 0.f, 0.f, 0.f);

    // prologue: prefetch tile 0
    int kbase = ks * 64;
    float4 pe  = E4[((rb * 64 + erow) * DD_ + kbase) / 4 + ec4];
    float4 pw0 = (wc0 < 16) ? W4g[((kbase + wkk0) * 64) / 4 + wc0]
                            : W4g[((DD_ + kbase + wkk0) * 64) / 4 + (wc0 - 16)];
    float4 pw1 = (wc0 < 16) ? W4g[((kbase + wkk0 + 8) * 64) / 4 + wc0]
                            : W4g[((DD_ + kbase + wkk0 + 8) * 64) / 4 + (wc0 - 16)];

    const float4* sET4 = reinterpret_cast<const float4*>(sET);
    const float4* sW4  = reinterpret_cast<const float4*>(sW);
    float4* sW4w = reinterpret_cast<float4*>(sW);

#pragma unroll
    for (int kt = 0; kt < 4; ++kt) {
        // store prefetched tile to smem
        sET[(ec4 * 4 + 0) * 68 + erow] = pe.x;
        sET[(ec4 * 4 + 1) * 68 + erow] = pe.y;
        sET[(ec4 * 4 + 2) * 68 + erow] = pe.z;
        sET[(ec4 * 4 + 3) * 68 + erow] = pe.w;
        sW4w[wkk0 * 32 + wc0]       = pw0;
        sW4w[(wkk0 + 8) * 32 + wc0] = pw1;
        __syncthreads();

        // prefetch next tile (overlaps with compute below)
        if (kt < 3) {
            const int kb = ks * 64 + (kt + 1) * 16;
            pe  = E4[((rb * 64 + erow) * DD_ + kb) / 4 + ec4];
            pw0 = (wc0 < 16) ? W4g[((kb + wkk0) * 64) / 4 + wc0]
                             : W4g[((DD_ + kb + wkk0) * 64) / 4 + (wc0 - 16)];
            pw1 = (wc0 < 16) ? W4g[((kb + wkk0 + 8) * 64) / 4 + wc0]
                             : W4g[((DD_ + kb + wkk0 + 8) * 64) / 4 + (wc0 - 16)];
        }

#pragma unroll
        for (int kk = 0; kk < 16; ++kk) {
            float4 w  = sW4[kk * 32 + lane];
            float4 e0 = sET4[kk * 17 + wrp * 2 + 0];  // rows wrp*8..+3
            float4 e1 = sET4[kk * 17 + wrp * 2 + 1];  // rows wrp*8+4..+7
            const float ev[8] = {e0.x, e0.y, e0.z, e0.w, e1.x, e1.y, e1.z, e1.w};
#pragma unroll
            for (int r = 0; r < 8; ++r) {
                acc[r].x = fmaf(ev[r], w.x, acc[r].x);
                acc[r].y = fmaf(ev[r], w.y, acc[r].y);
                acc[r].z = fmaf(ev[r], w.z, acc[r].z);
                acc[r].w = fmaf(ev[r], w.w, acc[r].w);
            }
        }
        __syncthreads();
    }

    float4* dst = reinterpret_cast<float4*>(g_part) + (size_t)ks * (NN_ * 32);
    const int rbase = rb * 64 + wrp * 8;
#pragma unroll
    for (int r = 0; r < 8; ++r)
        dst[(rbase + r) * 32 + lane] = acc[r];
}

// ---------------------------------------------------------------------------
// Kernel 2: reduce partials + fold geometry terms. grid 384, block (64,4).
// ---------------------------------------------------------------------------
__global__ __launch_bounds__(256) void fold_kernel(
    const float* __restrict__ pos, const float* __restrict__ prev,
    const float* __restrict__ W1, const float* __restrict__ b1)
{
    const int i = blockIdx.x * 4 + threadIdx.y;
    const int h = threadIdx.x;

    float suma = 0.f, sumb = 0.f;
#pragma unroll
    for (int s = 0; s < KSPLIT; ++s) {
        suma += g_part[(size_t)s * (NN_ * 128) + i * 128 + h];
        sumb += g_part[(size_t)s * (NN_ * 128) + i * 128 + 64 + h];
    }
    float px = pos[i * 3 + 0], py = pos[i * 3 + 1], pz = pos[i * 3 + 2];
    float vx = px - prev[i * 3 + 0];
    float vy = py - prev[i * 3 + 1];
    float vz = pz - prev[i * 3 + 2];

    const float* Ws = W1 + 2 * DD_ * 64;  // W1s rows (8 x 64)
    float g = px * Ws[0 * 64 + h] + py * Ws[1 * 64 + h] + pz * Ws[2 * 64 + h]
            + vx * Ws[4 * 64 + h] + vy * Ws[5 * 64 + h] + vz * Ws[6 * 64 + h]
            + py * Ws[7 * 64 + h];

    g_A[i * 64 + h] = suma - g;
    g_B[i * 64 + h] = sumb + g + b1[h];

    if (h == 0) {
        g_pv[i * 6 + 0] = px; g_pv[i * 6 + 1] = py; g_pv[i * 6 + 2] = pz;
        g_pv[i * 6 + 3] = vx; g_pv[i * 6 + 4] = vy; g_pv[i * 6 + 5] = vz;
    }
}

// ---------------------------------------------------------------------------
// Kernel 3: pairwise. grid (48, 48), block (16, 16). Each thread: 2x2 strided
// micro-tile i in {ty, ty+16}, j in {tx, tx+16}.
// Logits as softmax-invariant differences: delta_k = l_k - l_0 using
// W2d[h][k] = W2[h][k+1] - W2[h][0]  (3 accumulators per pair, not 4).
// ---------------------------------------------------------------------------
__global__ __launch_bounds__(256) void pair_kernel(
    const float* __restrict__ W1, const float* __restrict__ W2,
    const float* __restrict__ b2, float* __restrict__ out)
{
    __shared__ __align__(16) float sA[32 * 68];   // rows padded to 68 floats
    __shared__ __align__(16) float sB[32 * 68];
    __shared__ __align__(16) float4 sW2d[64];     // (d1,d2,d3,0) per h
    __shared__ __align__(16) float sW3[64];
    __shared__ float sPVi[32 * 6];
    __shared__ float sPVj[32 * 6];

    const int tx = threadIdx.x, ty = threadIdx.y;
    const int t  = ty * 16 + tx;
    const int i0 = blockIdx.y * 32;
    const int j0 = blockIdx.x * 32;

    for (int idx = t; idx < 512; idx += 256) {
        int r = idx >> 4, c = idx & 15;
        reinterpret_cast<float4*>(sA)[r * 17 + c] =
            reinterpret_cast<const float4*>(g_A)[(i0 + r) * 16 + c];
        reinterpret_cast<float4*>(sB)[r * 17 + c] =
            reinterpret_cast<const float4*>(g_B)[(j0 + r) * 16 + c];
    }
    if (t < 64) {
        float w0 = W2[t * 4 + 0];
        sW2d[t] = make_float4(W2[t * 4 + 1] - w0, W2[t * 4 + 2] - w0,
                              W2[t * 4 + 3] - w0, 0.f);
        sW3[t] = W1[(2 * DD_ + 3) * 64 + t];  // w3 = W1s row 3 (distance)
    }
    for (int idx = t; idx < 192; idx += 256) {
        sPVi[idx] = g_pv[i0 * 6 + idx];
        sPVj[idx] = g_pv[j0 * 6 + idx];
    }
    __syncthreads();

    // geometry for the 4 pairs
    float dist[4], clos[4], vdif[4];
#pragma unroll
    for (int p = 0; p < 2; ++p) {
        int ri = ty + p * 16;
        float pix = sPVi[ri * 6 + 0], piy = sPVi[ri * 6 + 1], piz = sPVi[ri * 6 + 2];
        float vix = sPVi[ri * 6 + 3], viy = sPVi[ri * 6 + 4], viz = sPVi[ri * 6 + 5];
#pragma unroll
        for (int q = 0; q < 2; ++q) {
            int rj = tx + q * 16;
            float rpx = sPVj[rj * 6 + 0] - pix;
            float rpy = sPVj[rj * 6 + 1] - piy;
            float rpz = sPVj[rj * 6 + 2] - piz;
            float rvx = sPVj[rj * 6 + 3] - vix;
            float rvy = sPVj[rj * 6 + 4] - viy;
            float rvz = sPVj[rj * 6 + 5] - viz;
            float d = sqrtf(rpx * rpx + rpy * rpy + rpz * rpz);
            float dot = rpx * rvx + rpy * rvy + rpz * rvz;
            int pq = p * 2 + q;
            dist[pq] = d;
            clos[pq] = -dot / fmaxf(d, 1e-6f);
            vdif[pq] = rpy;
        }
    }

    float acc1[4] = {0.f, 0.f, 0.f, 0.f};
    float acc2[4] = {0.f, 0.f, 0.f, 0.f};
    float acc3[4] = {0.f, 0.f, 0.f, 0.f};

    const float4* A4  = reinterpret_cast<const float4*>(sA);
    const float4* B4  = reinterpret_cast<const float4*>(sB);
    const float4* W34 = reinterpret_cast<const float4*>(sW3);

#pragma unroll 4
    for (int h4 = 0; h4 < 16; ++h4) {
        float4 af[2], bf[2];
        af[0] = A4[ty * 17 + h4];
        af[1] = A4[(ty + 16) * 17 + h4];
        bf[0] = B4[tx * 17 + h4];
        bf[1] = B4[(tx + 16) * 17 + h4];
        float4 w3v = W34[h4];
        float4 wd0 = sW2d[h4 * 4 + 0];
        float4 wd1 = sW2d[h4 * 4 + 1];
        float4 wd2 = sW2d[h4 * 4 + 2];
        float4 wd3 = sW2d[h4 * 4 + 3];

        const float aw[2][4] = {{af[0].x, af[0].y, af[0].z, af[0].w},
                                {af[1].x, af[1].y, af[1].z, af[1].w}};
        const float bw[2][4] = {{bf[0].x, bf[0].y, bf[0].z, bf[0].w},
                                {bf[1].x, bf[1].y, bf[1].z, bf[1].w}};
        const float w3a[4] = {w3v.x, w3v.y, w3v.z, w3v.w};
        const float4 wda[4] = {wd0, wd1, wd2, wd3};

#pragma unroll
        for (int hh = 0; hh < 4; ++hh) {
            const float w3h = w3a[hh];
            const float4 wd = wda[hh];
#pragma unroll
            for (int p = 0; p < 2; ++p) {
#pragma unroll
                for (int q = 0; q < 2; ++q) {
                    const int pq = p * 2 + q;
                    float tt = fmaf(dist[pq], w3h, aw[p][hh] + bw[q][hh]);
                    float r  = fmaxf(tt, 0.f);
                    acc1[pq] = fmaf(r, wd.x, acc1[pq]);
                    acc2[pq] = fmaf(r, wd.y, acc2[pq]);
                    acc3[pq] = fmaf(r, wd.z, acc3[pq]);
                }
            }
        }
    }

    const float db1 = __ldg(&b2[1]) - __ldg(&b2[0]);
    const float db2 = __ldg(&b2[2]) - __ldg(&b2[0]);
    const float db3 = __ldg(&b2[3]) - __ldg(&b2[0]);

#pragma unroll
    for (int p = 0; p < 2; ++p) {
#pragma unroll
        for (int q = 0; q < 2; ++q) {
            const int pq = p * 2 + q;
            float d1 = acc1[pq] + db1;
            float d2 = acc2[pq] + db2;
            float d3 = acc3[pq] + db3;
            float m = fmaxf(fmaxf(0.f, d1), fmaxf(d2, d3));
            float sum = __expf(0.f - m) + __expf(d1 - m)
                      + __expf(d2 - m) + __expf(d3 - m);
            float conf = __fdividef(1.0f, sum);
            int best = 0; float bm = 0.f;
            if (d1 > bm) { bm = d1; best = 1; }
            if (d2 > bm) { bm = d2; best = 2; }
            if (d3 > bm) { bm = d3; best = 3; }

            float d = dist[pq], c = clos[pq], v = vdif[pq];
            bool near  = d < 0.25f;
            bool appr  = !near && (c > 0.05f);
            bool flee  = !near && !appr && (c < -0.05f);
            bool above = !near && !appr && !flee && (fabsf(v) > 0.3f) && (d < 0.5f);

            int rt = near ? 0 : (appr ? 1 : (flee ? 2 : (above ? 3 : best)));
            float co = conf;
            if (near)              co = fmaxf(co, 0.8f);
            else if (appr || flee) co = fmaxf(co, 0.6f);
            else if (above)        co = fmaxf(co, 0.5f);

            int ig = i0 + ty + p * 16;
            int jg = j0 + tx + q * 16;
            size_t off = (size_t)ig * NN_ + jg;
            out[off]             = (float)rt;
            out[PLANE + off]     = co;
            out[2 * PLANE + off] = (jg > ig && co > 0.3f) ? 1.0f : 0.0f;
        }
    }
}

extern "C" void kernel_launch(void* const* d_in, const int* in_sizes, int n_in,
                              void* d_out, int out_size)
{
    const float* E    = (const float*)d_in[0];
    const float* pos  = (const float*)d_in[1];
    const float* prev = (const float*)d_in[2];
    const float* W1   = (const float*)d_in[3];
    const float* b1   = (const float*)d_in[4];
    const float* W2   = (const float*)d_in[5];
    const float* b2   = (const float*)d_in[6];
    float* out = (float*)d_out;

    gemm_partial_kernel<<<dim3(24, KSPLIT), 256>>>(E, W1);
    fold_kernel<<<NN_ / 4, dim3(64, 4)>>>(pos, prev, W1, b1);
    pair_kernel<<<dim3(48, 48), dim3(16, 16)>>>(W1, W2, b2, out);
}